// round 16
// baseline (speedup 1.0000x reference)
#include <cuda_runtime.h>
#include <cuda_bf16.h>
#include <cstdint>

// Problem constants: N=50000, E=600000, IN_DIM=128, HID=256, OUT=128
#define MAXN 50000
#define MAXE 600000
#define DIM 128
#define SCAN_BLK 512
#define MAX_SBLK 128

// Scratch (device globals — zero-initialized at load; gather/fill restore the
// zero invariant for g_deg/g_flagS at the end of every execution)
__device__ float g_msg[MAXN * DIM];
__device__ float g_partial[MAXN * DIM];     // h @ W[0:128]
__device__ int   g_deg[MAXN];
__device__ int   g_off[MAXN];
__device__ int   g_rank[MAXE];
__device__ int   g_csr[MAXE];
__device__ int   g_agg[MAX_SBLK];
__device__ int   g_flagS[MAX_SBLK];
__device__ __nv_bfloat16 g_Wh[256 * 128];
__device__ __nv_bfloat16 g_Wl[256 * 128];
__device__ float g_b[128];

static __device__ __forceinline__ uint32_t s2u(const void* p) {
    return (uint32_t)__cvta_generic_to_shared(p);
}

// ---------------------------------------------------------------------------
// Kernel (stream B): weight fusion. Blocks 0..255: W rows. Block 256: bias.
// ---------------------------------------------------------------------------
__global__ void fuse_weights(const float* __restrict__ W1, const float* __restrict__ b1,
                             const float* __restrict__ W2, const float* __restrict__ b2) {
    int row = blockIdx.x;
    int j = threadIdx.x;
    if (row < 256) {
        float acc = 0.f;
        #pragma unroll 4
        for (int k = 0; k < 256; k++)
            acc += W1[row * 256 + k] * W2[k * 128 + j];
        __nv_bfloat16 hi = __float2bfloat16(acc);
        __nv_bfloat16 lo = __float2bfloat16(acc - __bfloat162float(hi));
        g_Wh[row * 128 + j] = hi;
        g_Wl[row * 128 + j] = lo;
    } else {
        float acc = b2[j];
        #pragma unroll 4
        for (int k = 0; k < 256; k++)
            acc += b1[k] * W2[k * 128 + j];
        g_b[j] = acc;
    }
}

// ---------------------------------------------------------------------------
// Kernel (stream A): degree histogram; atomic return = edge rank.
// Relies on g_deg == 0 (zero-init first run; gather restores thereafter).
// ---------------------------------------------------------------------------
__global__ void histogram(const int* __restrict__ dst, int E) {
    int e = blockIdx.x * blockDim.x + threadIdx.x;
    if (e < E) g_rank[e] = atomicAdd(&g_deg[dst[e]], 1);
}

// ---------------------------------------------------------------------------
// Kernel (stream A): one-launch exclusive scan, shfl-based (4 barriers total).
// Relies on g_flagS == 0 (zero-init / fill_csr restores).
// ---------------------------------------------------------------------------
__global__ __launch_bounds__(SCAN_BLK) void scan_onepass(int n) {
    __shared__ int wsum[16];
    __shared__ int wred[16];
    __shared__ int base;
    int b = blockIdx.x, t = threadIdx.x;
    int lane = t & 31, w = t >> 5;
    int i = b * SCAN_BLK + t;
    int v = (i < n) ? g_deg[i] : 0;

    // inclusive warp scan
    int x = v;
    #pragma unroll
    for (int o = 1; o < 32; o <<= 1) {
        int y = __shfl_up_sync(0xffffffff, x, o);
        if (lane >= o) x += y;
    }
    if (lane == 31) wsum[w] = x;
    __syncthreads();
    // scan the 16 warp sums (warp 0)
    if (w == 0) {
        int s = (lane < 16) ? wsum[lane] : 0;
        #pragma unroll
        for (int o = 1; o < 16; o <<= 1) {
            int y = __shfl_up_sync(0xffffffff, s, o);
            if (lane >= o) s += y;
        }
        if (lane < 16) wsum[lane] = s;   // inclusive over warps
    }
    __syncthreads();
    int incl = x + ((w > 0) ? wsum[w - 1] : 0);

    if (t == 0) {
        g_agg[b] = wsum[15];             // block total
        __threadfence();
        atomicExch(&g_flagS[b], 1);
    }
    // decoupled lookback: thread t (< b) fetches predecessor t's aggregate
    int part = 0;
    if (t < b) {
        while (atomicAdd(&g_flagS[t], 0) == 0) {}
        part = g_agg[t];
    }
    #pragma unroll
    for (int o = 16; o > 0; o >>= 1)
        part += __shfl_down_sync(0xffffffff, part, o);
    if (lane == 0) wred[w] = part;
    __syncthreads();
    if (t == 0) {
        int s = 0;
        #pragma unroll
        for (int k = 0; k < 16; k++) s += wred[k];
        base = s;
    }
    __syncthreads();
    if (i < n) g_off[i] = base + incl - v;   // exclusive
}

// ---------------------------------------------------------------------------
// Kernel (stream A): atomic-free CSR fill; block 0 also restores g_flagS = 0
// (scan is complete before fill launches — flags no longer needed this run)
// ---------------------------------------------------------------------------
__global__ void fill_csr(const int* __restrict__ src, const int* __restrict__ dst, int E) {
    if (blockIdx.x == 0 && threadIdx.x < MAX_SBLK) g_flagS[threadIdx.x] = 0;
    int e = blockIdx.x * blockDim.x + threadIdx.x;
    if (e >= E) return;
    g_csr[g_off[dst[e]] + g_rank[e]] = src[e];
}

// ---------------------------------------------------------------------------
// Kernel (stream A): gather + mean over node range [n0, n1). One warp/node.
// Lane 0 restores g_deg[node] = 0 after use (sole consumer of deg).
// ---------------------------------------------------------------------------
__global__ void gather_csr(const float* __restrict__ h, int n0, int n1) {
    int warp = n0 + ((blockIdx.x * blockDim.x + threadIdx.x) >> 5);
    int lane = threadIdx.x & 31;
    if (warp >= n1) return;
    int beg = g_off[warp];
    int deg = g_deg[warp];
    if (lane == 0) g_deg[warp] = 0;      // restore zero invariant
    float4 acc = make_float4(0.f, 0.f, 0.f, 0.f);

    for (int i = 0; i < deg; i += 32) {
        int idx = (i + lane < deg) ? g_csr[beg + i + lane] : 0;
        int m = min(32, deg - i);
        #pragma unroll 4
        for (int j = 0; j < m; j++) {
            int s = __shfl_sync(0xffffffff, idx, j);
            float4 v = reinterpret_cast<const float4*>(h)[(size_t)s * (DIM / 4) + lane];
            acc.x += v.x; acc.y += v.y; acc.z += v.z; acc.w += v.w;
        }
    }
    float inv = 1.0f / fmaxf((float)deg, 1.0f);
    acc.x *= inv; acc.y *= inv; acc.z *= inv; acc.w *= inv;
    reinterpret_cast<float4*>(g_msg)[(size_t)warp * (DIM / 4) + lane] = acc;
}

// ---------------------------------------------------------------------------
// GEMM common (64x128 tile, bf16 3-way split), block offset blk0
// ---------------------------------------------------------------------------
#define GBM 64
#define GBK 32
#define LDA 40
#define LDB 136

#define MMA_B16(d, a, b)                                                        \
    asm volatile("mma.sync.aligned.m16n8k16.row.col.f32.bf16.bf16.f32 "         \
                 "{%0,%1,%2,%3}, {%4,%5,%6,%7}, {%8,%9}, {%0,%1,%2,%3};"        \
                 : "+f"(d[0]), "+f"(d[1]), "+f"(d[2]), "+f"(d[3])               \
                 : "r"(a[0]), "r"(a[1]), "r"(a[2]), "r"(a[3]),                  \
                   "r"(b[0]), "r"(b[1]))

template <bool ADD_PARTIAL>
__device__ __forceinline__ void gemm_half(const float* __restrict__ Asrc,
                                          float* __restrict__ outp, int M,
                                          int kcLo, int kcHi, int blk0) {
    __shared__ __nv_bfloat16 Ah[GBM * LDA], Al[GBM * LDA];
    __shared__ __nv_bfloat16 Bh[GBK * LDB], Bl[GBK * LDB];

    int tid = threadIdx.x;
    int lane = tid & 31;
    int warp = tid >> 5;
    int wm = (warp >> 2) * 32;
    int wn = (warp & 3) * 32;
    int row0 = (blockIdx.x + blk0) * GBM;

    float acc[2][4][4];
    #pragma unroll
    for (int mt = 0; mt < 2; mt++)
        #pragma unroll
        for (int nt = 0; nt < 4; nt++)
            #pragma unroll
            for (int r = 0; r < 4; r++) acc[mt][nt][r] = 0.f;

    for (int kc = kcLo; kc < kcHi; kc++) {
        int k0 = kc * GBK;
        int ka = k0 - kcLo * GBK;

        #pragma unroll
        for (int l = 0; l < 2; l++) {
            int idx = tid + l * 256;
            int r = idx >> 3;
            int c = (idx & 7) * 4;
            float4 v = make_float4(0.f, 0.f, 0.f, 0.f);
            int gr = row0 + r;
            if (gr < M) v = *reinterpret_cast<const float4*>(Asrc + (size_t)gr * DIM + ka + c);
            float f[4] = {v.x, v.y, v.z, v.w};
            __nv_bfloat16 h0 = __float2bfloat16(f[0]);
            __nv_bfloat16 h1 = __float2bfloat16(f[1]);
            __nv_bfloat16 h2 = __float2bfloat16(f[2]);
            __nv_bfloat16 h3 = __float2bfloat16(f[3]);
            __nv_bfloat162 hp0 = __nv_bfloat162(h0, h1);
            __nv_bfloat162 hp1 = __nv_bfloat162(h2, h3);
            __nv_bfloat162 lp0 = __nv_bfloat162(__float2bfloat16(f[0] - __bfloat162float(h0)),
                                                __float2bfloat16(f[1] - __bfloat162float(h1)));
            __nv_bfloat162 lp1 = __nv_bfloat162(__float2bfloat16(f[2] - __bfloat162float(h2)),
                                                __float2bfloat16(f[3] - __bfloat162float(h3)));
            *reinterpret_cast<__nv_bfloat162*>(&Ah[r * LDA + c])     = hp0;
            *reinterpret_cast<__nv_bfloat162*>(&Ah[r * LDA + c + 2]) = hp1;
            *reinterpret_cast<__nv_bfloat162*>(&Al[r * LDA + c])     = lp0;
            *reinterpret_cast<__nv_bfloat162*>(&Al[r * LDA + c + 2]) = lp1;
        }
        #pragma unroll
        for (int l = 0; l < 4; l++) {
            int idx = tid + l * 256;
            int r = idx >> 5;
            int c = (idx & 31) * 4;
            uint2 vh = *reinterpret_cast<const uint2*>(&g_Wh[(size_t)(k0 + r) * 128 + c]);
            uint2 vl = *reinterpret_cast<const uint2*>(&g_Wl[(size_t)(k0 + r) * 128 + c]);
            *reinterpret_cast<uint2*>(&Bh[r * LDB + c]) = vh;
            *reinterpret_cast<uint2*>(&Bl[r * LDB + c]) = vl;
        }
        __syncthreads();

        #pragma unroll
        for (int ks = 0; ks < 2; ks++) {
            uint32_t ah[2][4], al[2][4], bh[4][2], bl[4][2];
            #pragma unroll
            for (int mt = 0; mt < 2; mt++) {
                int r = wm + mt * 16 + (lane & 15);
                int eo = r * LDA + ks * 16 + ((lane >> 4) * 8);
                uint32_t ad = s2u(&Ah[eo]);
                asm volatile("ldmatrix.sync.aligned.m8n8.x4.shared.b16 {%0,%1,%2,%3}, [%4];"
                             : "=r"(ah[mt][0]), "=r"(ah[mt][1]), "=r"(ah[mt][2]), "=r"(ah[mt][3])
                             : "r"(ad));
                uint32_t ad2 = s2u(&Al[eo]);
                asm volatile("ldmatrix.sync.aligned.m8n8.x4.shared.b16 {%0,%1,%2,%3}, [%4];"
                             : "=r"(al[mt][0]), "=r"(al[mt][1]), "=r"(al[mt][2]), "=r"(al[mt][3])
                             : "r"(ad2));
            }
            #pragma unroll
            for (int nt = 0; nt < 4; nt++) {
                int kr = ks * 16 + (lane & 15);
                int eo = kr * LDB + wn + nt * 8;
                uint32_t bd = s2u(&Bh[eo]);
                asm volatile("ldmatrix.sync.aligned.m8n8.x2.trans.shared.b16 {%0,%1}, [%2];"
                             : "=r"(bh[nt][0]), "=r"(bh[nt][1]) : "r"(bd));
                uint32_t bd2 = s2u(&Bl[eo]);
                asm volatile("ldmatrix.sync.aligned.m8n8.x2.trans.shared.b16 {%0,%1}, [%2];"
                             : "=r"(bl[nt][0]), "=r"(bl[nt][1]) : "r"(bd2));
            }
            #pragma unroll
            for (int mt = 0; mt < 2; mt++)
                #pragma unroll
                for (int nt = 0; nt < 4; nt++) {
                    MMA_B16(acc[mt][nt], ah[mt], bh[nt]);
                    MMA_B16(acc[mt][nt], ah[mt], bl[nt]);
                    MMA_B16(acc[mt][nt], al[mt], bh[nt]);
                }
        }
        __syncthreads();
    }

    #pragma unroll
    for (int mt = 0; mt < 2; mt++) {
        int r0 = row0 + wm + mt * 16 + (lane >> 2);
        #pragma unroll
        for (int nt = 0; nt < 4; nt++) {
            int col = wn + nt * 8 + (lane & 3) * 2;
            if (ADD_PARTIAL) {
                float b0 = g_b[col], b1 = g_b[col + 1];
                if (r0 < M) {
                    float2 p = *reinterpret_cast<const float2*>(&g_partial[(size_t)r0 * DIM + col]);
                    float2 o;
                    o.x = fmaxf(acc[mt][nt][0] + p.x + b0, 0.f);
                    o.y = fmaxf(acc[mt][nt][1] + p.y + b1, 0.f);
                    *reinterpret_cast<float2*>(&outp[(size_t)r0 * DIM + col]) = o;
                }
                int r1 = r0 + 8;
                if (r1 < M) {
                    float2 p = *reinterpret_cast<const float2*>(&g_partial[(size_t)r1 * DIM + col]);
                    float2 o;
                    o.x = fmaxf(acc[mt][nt][2] + p.x + b0, 0.f);
                    o.y = fmaxf(acc[mt][nt][3] + p.y + b1, 0.f);
                    *reinterpret_cast<float2*>(&outp[(size_t)r1 * DIM + col]) = o;
                }
            } else {
                if (r0 < M)
                    *reinterpret_cast<float2*>(&outp[(size_t)r0 * DIM + col]) =
                        make_float2(acc[mt][nt][0], acc[mt][nt][1]);
                int r1 = r0 + 8;
                if (r1 < M)
                    *reinterpret_cast<float2*>(&outp[(size_t)r1 * DIM + col]) =
                        make_float2(acc[mt][nt][2], acc[mt][nt][3]);
            }
        }
    }
}

// Stream B: partial = h @ W[0:128]
__global__ __launch_bounds__(256, 3) void gemm_h(const float* __restrict__ h, int M) {
    gemm_half<false>(h, g_partial, M, 0, 4, 0);
}

// out = relu(partial + msg @ W[128:256] + b) over a block range
__global__ __launch_bounds__(256, 3) void gemm_msg(float* __restrict__ out, int M, int blk0) {
    gemm_half<true>(g_msg, out, M, 4, 8, blk0);
}

// ---------------------------------------------------------------------------
extern "C" void kernel_launch(void* const* d_in, const int* in_sizes, int n_in,
                              void* d_out, int out_size) {
    const float* h  = (const float*)d_in[0];
    const int* src  = (const int*)d_in[1];
    const int* dst  = (const int*)d_in[2];
    const float* W1 = (const float*)d_in[3];
    const float* b1 = (const float*)d_in[4];
    const float* W2 = (const float*)d_in[5];
    const float* b2 = (const float*)d_in[6];
    float* out = (float*)d_out;

    int N = in_sizes[0] / DIM;
    int E = in_sizes[1];
    int sblocks = (N + SCAN_BLK - 1) / SCAN_BLK;

    // 3-chunk gather/gemm pipeline, tail-weighted (boundaries multiple of 64)
    int c1 = (20992 < N) ? 20992 : N;
    int c2 = (41984 < N) ? 41984 : N;
    int blk1 = c1 / GBM;                          // 328
    int blk2 = (c2 - c1) / GBM;                   // 328
    int blk3 = (N - c2 + GBM - 1) / GBM;          // 126

    cudaStream_t sB;
    cudaEvent_t eFork, eH, eG1, eG2, eB;
    cudaStreamCreateWithFlags(&sB, cudaStreamNonBlocking);
    cudaEventCreateWithFlags(&eFork, cudaEventDisableTiming);
    cudaEventCreateWithFlags(&eH, cudaEventDisableTiming);
    cudaEventCreateWithFlags(&eG1, cudaEventDisableTiming);
    cudaEventCreateWithFlags(&eG2, cudaEventDisableTiming);
    cudaEventCreateWithFlags(&eB, cudaEventDisableTiming);

    cudaEventRecord(eFork, 0);
    cudaStreamWaitEvent(sB, eFork, 0);

    // Stream B: weight fusion + h-half GEMM (independent of aggregation)
    fuse_weights<<<257, 128, 0, sB>>>(W1, b1, W2, b2);
    gemm_h<<<(N + GBM - 1) / GBM, 256, 0, sB>>>(h, N);
    cudaEventRecord(eH, sB);

    // Stream A: aggregation chain (g_deg/g_flagS zero by invariant)
    histogram<<<(E + 255) / 256, 256>>>(dst, E);
    scan_onepass<<<sblocks, SCAN_BLK>>>(N);
    fill_csr<<<(E + 255) / 256, 256>>>(src, dst, E);

    // Gather chunks (stream A), events after chunks 1 & 2
    long long gt1 = (long long)c1 * 32;
    gather_csr<<<(int)((gt1 + 255) / 256), 256>>>(h, 0, c1);
    cudaEventRecord(eG1, 0);
    if (c2 > c1) {
        long long gt2 = (long long)(c2 - c1) * 32;
        gather_csr<<<(int)((gt2 + 255) / 256), 256>>>(h, c1, c2);
    }
    cudaEventRecord(eG2, 0);
    if (N > c2) {
        long long gt3 = (long long)(N - c2) * 32;
        gather_csr<<<(int)((gt3 + 255) / 256), 256>>>(h, c2, N);
    }

    // Stream B: msg-GEMM chunks 1 & 2 hidden under gathers 2 & 3
    cudaStreamWaitEvent(sB, eG1, 0);
    if (blk1 > 0) gemm_msg<<<blk1, 256, 0, sB>>>(out, N, 0);
    cudaStreamWaitEvent(sB, eG2, 0);
    if (blk2 > 0) gemm_msg<<<blk2, 256, 0, sB>>>(out, N, blk1);
    cudaEventRecord(eB, sB);

    // Stream A: tail msg-GEMM chunk (needs gemm_h's g_partial), then join B
    cudaStreamWaitEvent(0, eH, 0);
    if (blk3 > 0) gemm_msg<<<blk3, 256>>>(out, N, blk1 + blk2);
    cudaStreamWaitEvent(0, eB, 0);
}

// round 17
// speedup vs baseline: 1.4889x; 1.4889x over previous
#include <cuda_runtime.h>
#include <cuda_bf16.h>
#include <cstdint>

// Problem constants: N=50000, E=600000, IN_DIM=128, HID=256, OUT=128
#define MAXN 50000
#define MAXE 600000
#define DIM 128
#define SCAN_BLK 512
#define MAX_SBLK 128

// Scratch (device globals — zero-initialized at module load; the cleanup
// kernel restores the zero invariant at the end of every execution)
__device__ float g_msg[MAXN * DIM];
__device__ float g_partial[MAXN * DIM];     // h @ W[0:128]
__device__ int   g_deg[MAXN];
__device__ int   g_off[MAXN];
__device__ int   g_rank[MAXE];
__device__ int   g_csr[MAXE];
__device__ int   g_agg[MAX_SBLK];
__device__ int   g_flagS[MAX_SBLK];
__device__ __nv_bfloat16 g_Wh[256 * 128];
__device__ __nv_bfloat16 g_Wl[256 * 128];
__device__ float g_b[128];

static __device__ __forceinline__ uint32_t s2u(const void* p) {
    return (uint32_t)__cvta_generic_to_shared(p);
}

// ---------------------------------------------------------------------------
// Kernel (stream B): weight fusion. Blocks 0..255: W rows. Block 256: bias.
// ---------------------------------------------------------------------------
__global__ void fuse_weights(const float* __restrict__ W1, const float* __restrict__ b1,
                             const float* __restrict__ W2, const float* __restrict__ b2) {
    int row = blockIdx.x;
    int j = threadIdx.x;
    if (row < 256) {
        float acc = 0.f;
        #pragma unroll 4
        for (int k = 0; k < 256; k++)
            acc += W1[row * 256 + k] * W2[k * 128 + j];
        __nv_bfloat16 hi = __float2bfloat16(acc);
        __nv_bfloat16 lo = __float2bfloat16(acc - __bfloat162float(hi));
        g_Wh[row * 128 + j] = hi;
        g_Wl[row * 128 + j] = lo;
    } else {
        float acc = b2[j];
        #pragma unroll 4
        for (int k = 0; k < 256; k++)
            acc += b1[k] * W2[k * 128 + j];
        g_b[j] = acc;
    }
}

// ---------------------------------------------------------------------------
// Kernel (stream A): degree histogram; atomic return = edge rank.
// Relies on g_deg == 0 (zero-init first run; cleanup kernel thereafter).
// ---------------------------------------------------------------------------
__global__ void histogram(const int* __restrict__ dst, int E) {
    int e = blockIdx.x * blockDim.x + threadIdx.x;
    if (e < E) g_rank[e] = atomicAdd(&g_deg[dst[e]], 1);
}

// ---------------------------------------------------------------------------
// Kernel (stream A): one-launch exclusive scan, shfl-based (4 barriers;
// measured 6.0us vs 6.6us for the Hillis-Steele version).
// Relies on g_flagS == 0 (zero-init / cleanup restores).
// ---------------------------------------------------------------------------
__global__ __launch_bounds__(SCAN_BLK) void scan_onepass(int n) {
    __shared__ int wsum[16];
    __shared__ int wred[16];
    __shared__ int base;
    int b = blockIdx.x, t = threadIdx.x;
    int lane = t & 31, w = t >> 5;
    int i = b * SCAN_BLK + t;
    int v = (i < n) ? g_deg[i] : 0;

    // inclusive warp scan
    int x = v;
    #pragma unroll
    for (int o = 1; o < 32; o <<= 1) {
        int y = __shfl_up_sync(0xffffffff, x, o);
        if (lane >= o) x += y;
    }
    if (lane == 31) wsum[w] = x;
    __syncthreads();
    if (w == 0) {
        int s = (lane < 16) ? wsum[lane] : 0;
        #pragma unroll
        for (int o = 1; o < 16; o <<= 1) {
            int y = __shfl_up_sync(0xffffffff, s, o);
            if (lane >= o) s += y;
        }
        if (lane < 16) wsum[lane] = s;   // inclusive over warps
    }
    __syncthreads();
    int incl = x + ((w > 0) ? wsum[w - 1] : 0);

    if (t == 0) {
        g_agg[b] = wsum[15];             // block total
        __threadfence();
        atomicExch(&g_flagS[b], 1);
    }
    int part = 0;
    if (t < b) {
        while (atomicAdd(&g_flagS[t], 0) == 0) {}
        part = g_agg[t];
    }
    #pragma unroll
    for (int o = 16; o > 0; o >>= 1)
        part += __shfl_down_sync(0xffffffff, part, o);
    if (lane == 0) wred[w] = part;
    __syncthreads();
    if (t == 0) {
        int s = 0;
        #pragma unroll
        for (int k = 0; k < 16; k++) s += wred[k];
        base = s;
    }
    __syncthreads();
    if (i < n) g_off[i] = base + incl - v;   // exclusive
}

// ---------------------------------------------------------------------------
// Kernel (stream A): atomic-free CSR fill
// ---------------------------------------------------------------------------
__global__ void fill_csr(const int* __restrict__ src, const int* __restrict__ dst, int E) {
    int e = blockIdx.x * blockDim.x + threadIdx.x;
    if (e >= E) return;
    g_csr[g_off[dst[e]] + g_rank[e]] = src[e];
}

// ---------------------------------------------------------------------------
// Kernel (stream A): gather + mean over node range [n0, n1). One warp/node.
// ---------------------------------------------------------------------------
__global__ void gather_csr(const float* __restrict__ h, int n0, int n1) {
    int warp = n0 + ((blockIdx.x * blockDim.x + threadIdx.x) >> 5);
    int lane = threadIdx.x & 31;
    if (warp >= n1) return;
    int beg = g_off[warp];
    int deg = g_deg[warp];
    float4 acc = make_float4(0.f, 0.f, 0.f, 0.f);

    for (int i = 0; i < deg; i += 32) {
        int idx = (i + lane < deg) ? g_csr[beg + i + lane] : 0;
        int m = min(32, deg - i);
        #pragma unroll 4
        for (int j = 0; j < m; j++) {
            int s = __shfl_sync(0xffffffff, idx, j);
            float4 v = reinterpret_cast<const float4*>(h)[(size_t)s * (DIM / 4) + lane];
            acc.x += v.x; acc.y += v.y; acc.z += v.z; acc.w += v.w;
        }
    }
    float inv = 1.0f / fmaxf((float)deg, 1.0f);
    acc.x *= inv; acc.y *= inv; acc.z *= inv; acc.w *= inv;
    reinterpret_cast<float4*>(g_msg)[(size_t)warp * (DIM / 4) + lane] = acc;
}

// ---------------------------------------------------------------------------
// Kernel (stream B, end): restore zero invariant for next execution
// ---------------------------------------------------------------------------
__global__ void cleanup(int n) {
    int i = blockIdx.x * blockDim.x + threadIdx.x;
    if (i < n) g_deg[i] = 0;
    if (i < MAX_SBLK) g_flagS[i] = 0;
}

// ---------------------------------------------------------------------------
// GEMM common (R12 64x128 tile, bf16 3-way split), block offset blk0
// ---------------------------------------------------------------------------
#define GBM 64
#define GBK 32
#define LDA 40
#define LDB 136

#define MMA_B16(d, a, b)                                                        \
    asm volatile("mma.sync.aligned.m16n8k16.row.col.f32.bf16.bf16.f32 "         \
                 "{%0,%1,%2,%3}, {%4,%5,%6,%7}, {%8,%9}, {%0,%1,%2,%3};"        \
                 : "+f"(d[0]), "+f"(d[1]), "+f"(d[2]), "+f"(d[3])               \
                 : "r"(a[0]), "r"(a[1]), "r"(a[2]), "r"(a[3]),                  \
                   "r"(b[0]), "r"(b[1]))

template <bool ADD_PARTIAL>
__device__ __forceinline__ void gemm_half(const float* __restrict__ Asrc,
                                          float* __restrict__ outp, int M,
                                          int kcLo, int kcHi, int blk0) {
    __shared__ __nv_bfloat16 Ah[GBM * LDA], Al[GBM * LDA];
    __shared__ __nv_bfloat16 Bh[GBK * LDB], Bl[GBK * LDB];

    int tid = threadIdx.x;
    int lane = tid & 31;
    int warp = tid >> 5;
    int wm = (warp >> 2) * 32;
    int wn = (warp & 3) * 32;
    int row0 = (blockIdx.x + blk0) * GBM;

    float acc[2][4][4];
    #pragma unroll
    for (int mt = 0; mt < 2; mt++)
        #pragma unroll
        for (int nt = 0; nt < 4; nt++)
            #pragma unroll
            for (int r = 0; r < 4; r++) acc[mt][nt][r] = 0.f;

    for (int kc = kcLo; kc < kcHi; kc++) {
        int k0 = kc * GBK;
        int ka = k0 - kcLo * GBK;

        #pragma unroll
        for (int l = 0; l < 2; l++) {
            int idx = tid + l * 256;
            int r = idx >> 3;
            int c = (idx & 7) * 4;
            float4 v = make_float4(0.f, 0.f, 0.f, 0.f);
            int gr = row0 + r;
            if (gr < M) v = *reinterpret_cast<const float4*>(Asrc + (size_t)gr * DIM + ka + c);
            float f[4] = {v.x, v.y, v.z, v.w};
            __nv_bfloat16 h0 = __float2bfloat16(f[0]);
            __nv_bfloat16 h1 = __float2bfloat16(f[1]);
            __nv_bfloat16 h2 = __float2bfloat16(f[2]);
            __nv_bfloat16 h3 = __float2bfloat16(f[3]);
            __nv_bfloat162 hp0 = __nv_bfloat162(h0, h1);
            __nv_bfloat162 hp1 = __nv_bfloat162(h2, h3);
            __nv_bfloat162 lp0 = __nv_bfloat162(__float2bfloat16(f[0] - __bfloat162float(h0)),
                                                __float2bfloat16(f[1] - __bfloat162float(h1)));
            __nv_bfloat162 lp1 = __nv_bfloat162(__float2bfloat16(f[2] - __bfloat162float(h2)),
                                                __float2bfloat16(f[3] - __bfloat162float(h3)));
            *reinterpret_cast<__nv_bfloat162*>(&Ah[r * LDA + c])     = hp0;
            *reinterpret_cast<__nv_bfloat162*>(&Ah[r * LDA + c + 2]) = hp1;
            *reinterpret_cast<__nv_bfloat162*>(&Al[r * LDA + c])     = lp0;
            *reinterpret_cast<__nv_bfloat162*>(&Al[r * LDA + c + 2]) = lp1;
        }
        #pragma unroll
        for (int l = 0; l < 4; l++) {
            int idx = tid + l * 256;
            int r = idx >> 5;
            int c = (idx & 31) * 4;
            uint2 vh = *reinterpret_cast<const uint2*>(&g_Wh[(size_t)(k0 + r) * 128 + c]);
            uint2 vl = *reinterpret_cast<const uint2*>(&g_Wl[(size_t)(k0 + r) * 128 + c]);
            *reinterpret_cast<uint2*>(&Bh[r * LDB + c]) = vh;
            *reinterpret_cast<uint2*>(&Bl[r * LDB + c]) = vl;
        }
        __syncthreads();

        #pragma unroll
        for (int ks = 0; ks < 2; ks++) {
            uint32_t ah[2][4], al[2][4], bh[4][2], bl[4][2];
            #pragma unroll
            for (int mt = 0; mt < 2; mt++) {
                int r = wm + mt * 16 + (lane & 15);
                int eo = r * LDA + ks * 16 + ((lane >> 4) * 8);
                uint32_t ad = s2u(&Ah[eo]);
                asm volatile("ldmatrix.sync.aligned.m8n8.x4.shared.b16 {%0,%1,%2,%3}, [%4];"
                             : "=r"(ah[mt][0]), "=r"(ah[mt][1]), "=r"(ah[mt][2]), "=r"(ah[mt][3])
                             : "r"(ad));
                uint32_t ad2 = s2u(&Al[eo]);
                asm volatile("ldmatrix.sync.aligned.m8n8.x4.shared.b16 {%0,%1,%2,%3}, [%4];"
                             : "=r"(al[mt][0]), "=r"(al[mt][1]), "=r"(al[mt][2]), "=r"(al[mt][3])
                             : "r"(ad2));
            }
            #pragma unroll
            for (int nt = 0; nt < 4; nt++) {
                int kr = ks * 16 + (lane & 15);
                int eo = kr * LDB + wn + nt * 8;
                uint32_t bd = s2u(&Bh[eo]);
                asm volatile("ldmatrix.sync.aligned.m8n8.x2.trans.shared.b16 {%0,%1}, [%2];"
                             : "=r"(bh[nt][0]), "=r"(bh[nt][1]) : "r"(bd));
                uint32_t bd2 = s2u(&Bl[eo]);
                asm volatile("ldmatrix.sync.aligned.m8n8.x2.trans.shared.b16 {%0,%1}, [%2];"
                             : "=r"(bl[nt][0]), "=r"(bl[nt][1]) : "r"(bd2));
            }
            #pragma unroll
            for (int mt = 0; mt < 2; mt++)
                #pragma unroll
                for (int nt = 0; nt < 4; nt++) {
                    MMA_B16(acc[mt][nt], ah[mt], bh[nt]);
                    MMA_B16(acc[mt][nt], ah[mt], bl[nt]);
                    MMA_B16(acc[mt][nt], al[mt], bh[nt]);
                }
        }
        __syncthreads();
    }

    #pragma unroll
    for (int mt = 0; mt < 2; mt++) {
        int r0 = row0 + wm + mt * 16 + (lane >> 2);
        #pragma unroll
        for (int nt = 0; nt < 4; nt++) {
            int col = wn + nt * 8 + (lane & 3) * 2;
            if (ADD_PARTIAL) {
                float b0 = g_b[col], b1 = g_b[col + 1];
                if (r0 < M) {
                    float2 p = *reinterpret_cast<const float2*>(&g_partial[(size_t)r0 * DIM + col]);
                    float2 o;
                    o.x = fmaxf(acc[mt][nt][0] + p.x + b0, 0.f);
                    o.y = fmaxf(acc[mt][nt][1] + p.y + b1, 0.f);
                    *reinterpret_cast<float2*>(&outp[(size_t)r0 * DIM + col]) = o;
                }
                int r1 = r0 + 8;
                if (r1 < M) {
                    float2 p = *reinterpret_cast<const float2*>(&g_partial[(size_t)r1 * DIM + col]);
                    float2 o;
                    o.x = fmaxf(acc[mt][nt][2] + p.x + b0, 0.f);
                    o.y = fmaxf(acc[mt][nt][3] + p.y + b1, 0.f);
                    *reinterpret_cast<float2*>(&outp[(size_t)r1 * DIM + col]) = o;
                }
            } else {
                if (r0 < M)
                    *reinterpret_cast<float2*>(&outp[(size_t)r0 * DIM + col]) =
                        make_float2(acc[mt][nt][0], acc[mt][nt][1]);
                int r1 = r0 + 8;
                if (r1 < M)
                    *reinterpret_cast<float2*>(&outp[(size_t)r1 * DIM + col]) =
                        make_float2(acc[mt][nt][2], acc[mt][nt][3]);
            }
        }
    }
}

// Stream B: partial = h @ W[0:128]
__global__ __launch_bounds__(256, 3) void gemm_h(const float* __restrict__ h, int M) {
    gemm_half<false>(h, g_partial, M, 0, 4, 0);
}

// out = relu(partial + msg @ W[128:256] + b) over a block range
__global__ __launch_bounds__(256, 3) void gemm_msg(float* __restrict__ out, int M, int blk0) {
    gemm_half<true>(g_msg, out, M, 4, 8, blk0);
}

// ---------------------------------------------------------------------------
extern "C" void kernel_launch(void* const* d_in, const int* in_sizes, int n_in,
                              void* d_out, int out_size) {
    const float* h  = (const float*)d_in[0];
    const int* src  = (const int*)d_in[1];
    const int* dst  = (const int*)d_in[2];
    const float* W1 = (const float*)d_in[3];
    const float* b1 = (const float*)d_in[4];
    const float* W2 = (const float*)d_in[5];
    const float* b2 = (const float*)d_in[6];
    float* out = (float*)d_out;

    int N = in_sizes[0] / DIM;
    int E = in_sizes[1];
    int sblocks = (N + SCAN_BLK - 1) / SCAN_BLK;

    // Node split for the gather/gemm pipeline (64-aligned) — R15 measured DAG
    int Nh = ((N / 2 + GBM - 1) / GBM) * GBM;        // 25024
    if (Nh > N) Nh = N;
    int blocks1 = Nh / GBM;                           // 391
    int blocks2 = (N - Nh + GBM - 1) / GBM;           // 391

    cudaStream_t sB;
    cudaEvent_t eFork, eG1, eG2, eB2;
    cudaStreamCreateWithFlags(&sB, cudaStreamNonBlocking);
    cudaEventCreateWithFlags(&eFork, cudaEventDisableTiming);
    cudaEventCreateWithFlags(&eG1, cudaEventDisableTiming);
    cudaEventCreateWithFlags(&eG2, cudaEventDisableTiming);
    cudaEventCreateWithFlags(&eB2, cudaEventDisableTiming);

    cudaEventRecord(eFork, 0);
    cudaStreamWaitEvent(sB, eFork, 0);

    // Stream B: weight fusion + h-half GEMM (independent of aggregation)
    fuse_weights<<<257, 128, 0, sB>>>(W1, b1, W2, b2);
    gemm_h<<<(N + GBM - 1) / GBM, 256, 0, sB>>>(h, N);

    // Stream A (default): aggregation chain (g_deg/g_flagS zero by invariant)
    histogram<<<(E + 255) / 256, 256>>>(dst, E);
    scan_onepass<<<sblocks, SCAN_BLK>>>(N);
    fill_csr<<<(E + 255) / 256, 256>>>(src, dst, E);

    long long gt1 = (long long)Nh * 32;
    gather_csr<<<(int)((gt1 + 255) / 256), 256>>>(h, 0, Nh);
    cudaEventRecord(eG1, 0);

    long long gt2 = (long long)(N - Nh) * 32;
    gather_csr<<<(int)((gt2 + 255) / 256), 256>>>(h, Nh, N);
    cudaEventRecord(eG2, 0);

    // Stream B: first-half msg GEMM overlapped with gather(half2),
    // then cleanup (restores zero invariant) overlapped with gemm_msg(half2)
    cudaStreamWaitEvent(sB, eG1, 0);
    gemm_msg<<<blocks1, 256, 0, sB>>>(out, N, 0);
    cudaStreamWaitEvent(sB, eG2, 0);
    cleanup<<<(N + 255) / 256, 256, 0, sB>>>(N);
    cudaEventRecord(eB2, sB);

    // Stream A: second-half msg GEMM, then join stream B
    gemm_msg<<<blocks2, 256>>>(out, N, blocks1);
    cudaStreamWaitEvent(0, eB2, 0);
}